// round 17
// baseline (speedup 1.0000x reference)
#include <cuda_runtime.h>
#include <cuda_bf16.h>

// RWKV single-token inference, fp32 — persistent kernel (148x256).
// R17: fine-grained work units to kill ceil-quantization waste.
//  Phase A: 1KB quarter-row units (12288), atomicAdd partials into g_kvr.
//  Phase C: 2KB half-row units (10240), atomicAdd partials into raw kk/r2;
//           relu^2 / sigmoid applied by consumers.
//  WKV epilogue: redundant per-block in phase B (from raw g_kvr).
//  B, D, head: R10 shapes. Depth-3 cp.async pipeline with exact tail waits.
// D=1024, H=4096, L=24, V=50277.

#define D    1024
#define HD   4096
#define NL   24
#define NV   50277
#define GRID 148
#define NTH  256
#define NWARP 8
#define TOTW (GRID * NWARP)   // 1184

#define SBUF_F   4096                  // 16KB shared vector region (floats)
#define WBUF_F   3072                  // 12KB per-warp staging (floats)
#define SMEM_DYN ((SBUF_F + NWARP * WBUF_F) * 4)   // 112KB

__device__ __align__(16) float g_x[D];
__device__ __align__(16) float g_kvr[3 * D];   // raw k|v|r sums (atomic)
__device__ __align__(16) float g_kkraw[HD];    // raw fkw sums (atomic)
__device__ __align__(16) float g_r2raw[D];     // raw frw sums (atomic)
__device__ __align__(16) float g_state_scratch[NL * 5 * D];
__device__ unsigned g_count;
__device__ unsigned g_gen;

__device__ __forceinline__ float warp_sum(float s) {
#pragma unroll
    for (int o = 16; o > 0; o >>= 1) s += __shfl_xor_sync(0xffffffffu, s, o);
    return s;
}

// Grid barrier (148 co-resident blocks).
__device__ __forceinline__ void grid_barrier() {
    __syncthreads();
    if (threadIdx.x == 0) {
        unsigned gen;
        asm volatile("ld.global.relaxed.gpu.u32 %0, [%1];" : "=r"(gen) : "l"(&g_gen));
        unsigned old;
        asm volatile("atom.global.add.acq_rel.gpu.u32 %0, [%1], 1;"
                     : "=r"(old) : "l"(&g_count) : "memory");
        if (old == GRID - 1) {
            asm volatile("st.global.relaxed.gpu.u32 [%0], %1;" :: "l"(&g_count), "r"(0u) : "memory");
            asm volatile("st.global.release.gpu.u32 [%0], %1;" :: "l"(&g_gen), "r"(gen + 1u) : "memory");
        } else {
            unsigned cur;
            do {
                __nanosleep(20);
                asm volatile("ld.global.acquire.gpu.u32 %0, [%1];" : "=r"(cur) : "l"(&g_gen) : "memory");
            } while (cur == gen);
        }
    }
    __syncthreads();
}

// cp.async of SZ16 *16-byte units per lane* (SZ16=2:1KB, 4:2KB, 8:4KB).
template <int SZ16>
__device__ __forceinline__ void cpa_unit(unsigned dst, const float* __restrict__ src, int lane) {
    unsigned d = dst + (unsigned)lane * 16u;
    const char* s = (const char*)src + lane * 16;
#pragma unroll
    for (int j = 0; j < SZ16; j++)
        asm volatile("cp.async.cg.shared.global [%0], [%1], 16;"
                     :: "r"(d + 512u * j), "l"(s + 512 * j) : "memory");
}
#define CPA_COMMIT() asm volatile("cp.async.commit_group;" ::: "memory")
#define CPA_WAIT(n)  asm volatile("cp.async.wait_group %0;" :: "n"(n) : "memory")
// Runtime-depth wait (depth is warp-uniform).
__device__ __forceinline__ void cpa_wait_depth(int depth) {
    if (depth >= 2) { CPA_WAIT(2); }
    else if (depth == 1) { CPA_WAIT(1); }
    else { CPA_WAIT(0); }
}

// dot over J float4 per lane (row span = 32*J floats... J=2:256f, 4:512f, 8:1024f)
template <int J>
__device__ __forceinline__ float dotJ(const float4* __restrict__ w4,
                                      const float4* __restrict__ v4, int lane) {
    float s = 0.f;
#pragma unroll
    for (int j = 0; j < J; j++) {
        float4 a = w4[lane + 32 * j];
        float4 b = v4[lane + 32 * j];
        s = fmaf(a.x, b.x, s); s = fmaf(a.y, b.y, s);
        s = fmaf(a.z, b.z, s); s = fmaf(a.w, b.w, s);
    }
    return s;
}

// Fused single-pass LN over g_x.
__device__ __forceinline__ void ln_fused(const float* __restrict__ w,
                                         const float* __restrict__ b,
                                         float* sred, float out[4]) {
    int t = threadIdx.x;
    int warp = t >> 5;
    int lane = t & 31;
    float4 xv = __ldcg((const float4*)g_x + t);
    float s = xv.x + xv.y + xv.z + xv.w;
    float q = xv.x * xv.x + xv.y * xv.y + xv.z * xv.z + xv.w * xv.w;
    __syncthreads();
#pragma unroll
    for (int o = 16; o > 0; o >>= 1) {
        s += __shfl_xor_sync(0xffffffffu, s, o);
        q += __shfl_xor_sync(0xffffffffu, q, o);
    }
    if (lane == 0) { sred[warp] = s; sred[NWARP + warp] = q; }
    __syncthreads();
    float ts = 0.f, tq = 0.f;
#pragma unroll
    for (int ww = 0; ww < NWARP; ww++) { ts += sred[ww]; tq += sred[NWARP + ww]; }
    float mu = ts * (1.f / D);
    float var = tq * (1.f / D) - mu * mu;
    float rstd = rsqrtf(var + 1e-5f);
    float xa[4]; *(float4*)xa = xv;
    float wa[4], ba[4];
    *(float4*)wa = ((const float4*)w)[t];
    *(float4*)ba = ((const float4*)b)[t];
#pragma unroll
    for (int c = 0; c < 4; c++) out[c] = (xa[c] - mu) * rstd * wa[c] + ba[c];
}

__global__ __launch_bounds__(NTH, 1) void rwkv_fused(
    const int* __restrict__ token, const float* __restrict__ state,
    const float* __restrict__ emb,
    const float* __restrict__ ln0_w, const float* __restrict__ ln0_b,
    const float* __restrict__ ln1_w, const float* __restrict__ ln1_b,
    const float* __restrict__ ln2_w, const float* __restrict__ ln2_b,
    const float* __restrict__ kw, const float* __restrict__ vw,
    const float* __restrict__ rw, const float* __restrict__ ow,
    const float* __restrict__ mk, const float* __restrict__ mv,
    const float* __restrict__ mr,
    const float* __restrict__ tf, const float* __restrict__ td,
    const float* __restrict__ fkw, const float* __restrict__ fvw,
    const float* __restrict__ frw,
    const float* __restrict__ fmk, const float* __restrict__ fmr,
    const float* __restrict__ lnw, const float* __restrict__ lnb,
    const float* __restrict__ head,
    float* __restrict__ logits, float* __restrict__ state_out) {
    __shared__ float sred[2 * NWARP];
    extern __shared__ __align__(16) float dsm[];
    float* s_vec = dsm;                                             // 16KB
    float* wbuf  = dsm + SBUF_F + (threadIdx.x >> 5) * WBUF_F;       // 12KB/warp
    const unsigned wbu = (unsigned)__cvta_generic_to_shared(wbuf);

    const int t = threadIdx.x, warp = t >> 5, lane = t & 31, bid = blockIdx.x;
    const int wg = bid * NWARP + warp;          // 0..1183
    const bool rowact = (wg < D);

    // ---- kernel start: bid1 zeros g_kvr (layer-0 phase A accumulators) ----
    if (bid == 1) {
        for (int i = t; i < 3 * D / 4; i += NTH)
            ((float4*)g_kvr)[i] = make_float4(0.f, 0.f, 0.f, 0.f);
    }

    // ---- embed: block 0 computes g_x = LN0(emb[token]) ----
    if (bid == 0) {
        float4 xv = ((const float4*)(emb + (size_t)token[0] * D))[t];
        float s = xv.x + xv.y + xv.z + xv.w;
        float q = xv.x * xv.x + xv.y * xv.y + xv.z * xv.z + xv.w * xv.w;
#pragma unroll
        for (int o = 16; o > 0; o >>= 1) {
            s += __shfl_xor_sync(0xffffffffu, s, o);
            q += __shfl_xor_sync(0xffffffffu, q, o);
        }
        if (lane == 0) { sred[warp] = s; sred[NWARP + warp] = q; }
        __syncthreads();
        float ts = 0.f, tq = 0.f;
#pragma unroll
        for (int ww = 0; ww < NWARP; ww++) { ts += sred[ww]; tq += sred[NWARP + ww]; }
        float mu = ts * (1.f / D);
        float var = tq * (1.f / D) - mu * mu;
        float rstd = rsqrtf(var + 1e-5f);
        float4 wv = ((const float4*)ln0_w)[t];
        float4 bv = ((const float4*)ln0_b)[t];
        float4 o;
        o.x = (xv.x - mu) * rstd * wv.x + bv.x;
        o.y = (xv.y - mu) * rstd * wv.y + bv.y;
        o.z = (xv.z - mu) * rstd * wv.z + bv.z;
        o.w = (xv.w - mu) * rstd * wv.w + bv.w;
        ((float4*)g_x)[t] = o;
    }

    // Unit counts (warp-uniform).
    const int nA = (wg < 448) ? 11 : 10;   // 12288 = 10*1184 + 448
    const int nC = (wg < 768) ? 9 : 8;     // 10240 = 8*1184 + 768
    const int nH = (wg < 549) ? 43 : 42;   // 50277 = 42*1184 + 549

    // Unit source address helpers.
#define A_SRC(u, loW) ((((u) >> 12) == 0 ? kw : ((u) >> 12) == 1 ? vw : rw) \
                       + (loW) + (size_t)(((u) >> 2) & 1023) * D + (((u) & 3) << 8))
#define C_SRC(u, l, loW) (((u) < 2 * HD) \
    ? fkw + (size_t)(l) * HD * D + (size_t)((u) >> 1) * D + (((u) & 1) << 9) \
    : frw + (loW) + (size_t)(((u) - 2 * HD) >> 1) * D + (((u) & 1) << 9))

    for (int l = 0; l < NL; l++) {
        const size_t lo = (size_t)l * D;
        const size_t loW = lo * D;
        const size_t sb = (size_t)l * 5 * D;
        const float* fv_row = fvw + (size_t)l * D * HD + (size_t)wg * HD;

        // ---- layer top: prefill phase A (3 x 1KB units) ----
#pragma unroll
        for (int i = 0; i < 3; i++) {
            if (i < nA) {
                cpa_unit<2>(wbu + (unsigned)i * 1024u, A_SRC(wg + i * TOTW, loW), lane);
                CPA_COMMIT();
            }
        }

        // ================= Phase A: k/v/r partial matvecs =================
        grid_barrier();   // g_x final
        {
            float xn4[4];
            ln_fused(ln1_w + lo, ln1_b + lo, sred, xn4);
            float mka[4], mva[4], mra[4], sxa[4];
            *(float4*)mka = ((const float4*)(mk + lo))[t];
            *(float4*)mva = ((const float4*)(mv + lo))[t];
            *(float4*)mra = ((const float4*)(mr + lo))[t];
            *(float4*)sxa = ((const float4*)(state + sb + D))[t];  // sx_att
            int base = 4 * t;
#pragma unroll
            for (int c = 0; c < 4; c++) {
                float xn = xn4[c];
                s_vec[base + c]         = xn * mka[c] + sxa[c] * (1.f - mka[c]);
                s_vec[D + base + c]     = xn * mva[c] + sxa[c] * (1.f - mva[c]);
                s_vec[2 * D + base + c] = xn * mra[c] + sxa[c] * (1.f - mra[c]);
                if (bid == 0) state_out[sb + D + base + c] = xn;   // state row 1
            }
            __syncthreads();

            for (int i = 0; i < nA; i++) {
                int depth = nA - 1 - i; if (depth > 2) depth = 2;
                cpa_wait_depth(depth);
                int u = wg + i * TOTW;
                int mat = u >> 12, rq = u & 4095;
                const float4* wsl = (const float4*)(wbuf + (i % 3) * 256);
                const float4* xs = (const float4*)(s_vec + (mat << 10) + ((rq & 3) << 8));
                float s = warp_sum(dotJ<2>(wsl, xs, lane));
                if (lane == 0) atomicAdd(&g_kvr[(mat << 10) + (rq >> 2)], s);
                int i3 = i + 3;
                if (i3 < nA) {
                    cpa_unit<2>(wbu + (unsigned)(i3 % 3) * 1024u, A_SRC(wg + i3 * TOTW, loW), lane);
                    CPA_COMMIT();
                }
            }
        }
        // prefill phase B (one 4KB row if rowact)
        if (rowact) {
            cpa_unit<8>(wbu, ow + loW + (size_t)wg * D, lane);
            CPA_COMMIT();
        }

        // ================= Phase B: WKV epilogue + ow matvec =================
        grid_barrier();   // g_kvr complete
        {
            // bid1 zeros next-phase accumulators (visible by C barrier)
            if (bid == 1) {
                for (int i = t; i < HD / 4; i += NTH)
                    ((float4*)g_kkraw)[i] = make_float4(0.f, 0.f, 0.f, 0.f);
                for (int i = t; i < D / 4; i += NTH)
                    ((float4*)g_r2raw)[i] = make_float4(0.f, 0.f, 0.f, 0.f);
            }
            // Redundant per-block WKV epilogue -> s_vec[0..1023] = r*wkv
            float ka[4], va[4], ra[4], aa[4], bb[4], pp[4], tfa[4], tda[4];
            *(float4*)ka = __ldcg((const float4*)g_kvr + t);
            *(float4*)va = __ldcg((const float4*)(g_kvr + D) + t);
            *(float4*)ra = __ldcg((const float4*)(g_kvr + 2 * D) + t);
            *(float4*)aa = ((const float4*)(state + sb + 2 * D))[t];
            *(float4*)bb = ((const float4*)(state + sb + 3 * D))[t];
            *(float4*)pp = ((const float4*)(state + sb + 4 * D))[t];
            *(float4*)tfa = ((const float4*)(tf + lo))[t];
            *(float4*)tda = ((const float4*)(td + lo))[t];
            int base = 4 * t;
#pragma unroll
            for (int c = 0; c < 4; c++) {
                float k = ka[c];
                float v = va[c];
                float rs = 1.f / (1.f + expf(-ra[c]));
                float ww = tfa[c] + k;
                float qq = fmaxf(pp[c], ww);
                float e1 = expf(pp[c] - qq);
                float e2 = expf(ww - qq);
                s_vec[base + c] = rs * (e1 * aa[c] + e2 * v) / (e1 * bb[c] + e2);
                if (bid == 0) {
                    float ww2 = pp[c] + tda[c];
                    float qq2 = fmaxf(ww2, k);
                    float e1b = expf(ww2 - qq2);
                    float e2b = expf(k - qq2);
                    state_out[sb + 2 * D + base + c] = e1b * aa[c] + e2b * v;
                    state_out[sb + 3 * D + base + c] = e1b * bb[c] + e2b;
                    state_out[sb + 4 * D + base + c] = qq2;
                }
            }
            __syncthreads();

            if (rowact) {
                CPA_WAIT(0);
                float s = warp_sum(dotJ<8>((const float4*)wbuf, (const float4*)s_vec, lane));
                if (lane == 0) g_x[wg] = __ldcg(g_x + wg) + s;
            }
        }
        // prefill phase C (3 x 2KB units)
#pragma unroll
        for (int i = 0; i < 3; i++) {
            if (i < nC) {
                cpa_unit<4>(wbu + (unsigned)i * 2048u, C_SRC(wg + i * TOTW, l, loW), lane);
                CPA_COMMIT();
            }
        }

        // ================= Phase C: channel mix 1 (partials) =================
        grid_barrier();   // g_x updated
        {
            // bid1 zeros g_kvr for next layer's phase A
            if (bid == 1) {
                for (int i = t; i < 3 * D / 4; i += NTH)
                    ((float4*)g_kvr)[i] = make_float4(0.f, 0.f, 0.f, 0.f);
            }
            float xn4[4];
            ln_fused(ln2_w + lo, ln2_b + lo, sred, xn4);
            float mka[4], mra[4], sxa[4];
            *(float4*)mka = ((const float4*)(fmk + lo))[t];
            *(float4*)mra = ((const float4*)(fmr + lo))[t];
            *(float4*)sxa = ((const float4*)(state + sb))[t];      // sx_ffn
            int base = 4 * t;
#pragma unroll
            for (int c = 0; c < 4; c++) {
                float xn = xn4[c];
                s_vec[base + c]     = xn * mka[c] + sxa[c] * (1.f - mka[c]);
                s_vec[D + base + c] = xn * mra[c] + sxa[c] * (1.f - mra[c]);
                if (bid == 0) state_out[sb + base + c] = xn;       // state row 0
            }
            __syncthreads();

            for (int i = 0; i < nC; i++) {
                int depth = nC - 1 - i; if (depth > 2) depth = 2;
                cpa_wait_depth(depth);
                int u = wg + i * TOTW;
                bool fk = (u < 2 * HD);
                const float4* wsl = (const float4*)(wbuf + (i % 3) * 512);
                const float4* xs = fk ? (const float4*)(s_vec + ((u & 1) << 9))
                                      : (const float4*)(s_vec + D + ((u & 1) << 9));
                float s = warp_sum(dotJ<4>(wsl, xs, lane));
                if (lane == 0) {
                    if (fk) atomicAdd(&g_kkraw[u >> 1], s);
                    else    atomicAdd(&g_r2raw[(u - 2 * HD) >> 1], s);
                }
                int i3 = i + 3;
                if (i3 < nC) {
                    cpa_unit<4>(wbu + (unsigned)(i3 % 3) * 2048u, C_SRC(wg + i3 * TOTW, l, loW), lane);
                    CPA_COMMIT();
                }
            }
        }
        // prefill phase D (2 x 4KB chunks of row wg)
        if (rowact) {
            cpa_unit<8>(wbu,          fv_row,        lane); CPA_COMMIT();
            cpa_unit<8>(wbu + 4096u,  fv_row + 1024, lane); CPA_COMMIT();
        }

        // ================= Phase D: x += r2 * (fvw @ kk) =================
        grid_barrier();   // raw kk/r2 complete
        {
            // load kk into smem applying relu^2
#pragma unroll
            for (int j = 0; j < 4; j++) {
                float4 v = __ldcg((const float4*)g_kkraw + t + NTH * j);
                float4 o;
                o.x = fmaxf(v.x, 0.f); o.x *= o.x;
                o.y = fmaxf(v.y, 0.f); o.y *= o.y;
                o.z = fmaxf(v.z, 0.f); o.z *= o.z;
                o.w = fmaxf(v.w, 0.f); o.w *= o.w;
                ((float4*)s_vec)[t + NTH * j] = o;
            }
            __syncthreads();
            if (rowact) {
                const float4* k4 = (const float4*)s_vec;
                CPA_WAIT(1);
                float s = dotJ<8>((const float4*)wbuf, k4, lane);
                cpa_unit<8>(wbu + 8192u, fv_row + 2048, lane); CPA_COMMIT();
                CPA_WAIT(1);
                s += dotJ<8>((const float4*)(wbuf + 1024), k4 + 256, lane);
                cpa_unit<8>(wbu, fv_row + 3072, lane); CPA_COMMIT();
                CPA_WAIT(1);
                s += dotJ<8>((const float4*)(wbuf + 2048), k4 + 512, lane);
                CPA_WAIT(0);
                s += dotJ<8>((const float4*)wbuf, k4 + 768, lane);
                s = warp_sum(s);
                if (lane == 0) {
                    float r2 = 1.f / (1.f + expf(-__ldcg(g_r2raw + wg)));
                    g_x[wg] = __ldcg(g_x + wg) + r2 * s;
                }
            }
        }
    }

    // ================= Head: logits = head @ LN(x) =================
#pragma unroll
    for (int i = 0; i < 3; i++) {
        cpa_unit<8>(wbu + (unsigned)i * 4096u, head + (size_t)(wg + i * TOTW) * D, lane);
        CPA_COMMIT();
    }
    grid_barrier();   // g_x final
    {
        float xn4[4];
        ln_fused(lnw, lnb, sred, xn4);
        int base = 4 * t;
#pragma unroll
        for (int c = 0; c < 4; c++) s_vec[base + c] = xn4[c];
        __syncthreads();

        const float4* x4 = (const float4*)s_vec;
        for (int i = 0; i < nH; i++) {
            int depth = nH - 1 - i; if (depth > 2) depth = 2;
            cpa_wait_depth(depth);
            int v = wg + i * TOTW;
            const float4* wsl = (const float4*)(wbuf + (i % 3) * 1024);
            float s = warp_sum(dotJ<8>(wsl, x4, lane));
            int i3 = i + 3;
            if (i3 < nH) {
                cpa_unit<8>(wbu + (unsigned)(i3 % 3) * 4096u,
                            head + (size_t)(wg + i3 * TOTW) * D, lane);
                CPA_COMMIT();
            }
            if (lane == 0) logits[v] = s;
        }
    }
}

// ---------------------------------------------------------------------------
extern "C" void kernel_launch(void* const* d_in, const int* in_sizes, int n_in,
                              void* d_out, int out_size) {
    const int*   token     = (const int*)d_in[0];
    const float* state     = (const float*)d_in[1];
    const float* emb       = (const float*)d_in[2];
    const float* ln0_w     = (const float*)d_in[3];
    const float* ln0_b     = (const float*)d_in[4];
    const float* ln1_w     = (const float*)d_in[5];
    const float* ln1_b     = (const float*)d_in[6];
    const float* ln2_w     = (const float*)d_in[7];
    const float* ln2_b     = (const float*)d_in[8];
    const float* att_key   = (const float*)d_in[9];
    const float* att_value = (const float*)d_in[10];
    const float* att_recep = (const float*)d_in[11];
    const float* att_out   = (const float*)d_in[12];
    const float* tm_k      = (const float*)d_in[13];
    const float* tm_v      = (const float*)d_in[14];
    const float* tm_r      = (const float*)d_in[15];
    const float* t_first   = (const float*)d_in[16];
    const float* t_decay   = (const float*)d_in[17];
    const float* ffn_key   = (const float*)d_in[18];
    const float* ffn_value = (const float*)d_in[19];
    const float* ffn_recep = (const float*)d_in[20];
    const float* ffn_tm_k  = (const float*)d_in[21];
    const float* ffn_tm_r  = (const float*)d_in[22];
    const float* lnout_w   = (const float*)d_in[23];
    const float* lnout_b   = (const float*)d_in[24];
    const float* head      = (const float*)d_in[25];

    float* out = (float*)d_out;
    float* logits = out;
    float* state_out;
    if (out_size >= NV + NL * 5 * D) {
        state_out = out + NV;
    } else {
        void* p = nullptr;
        cudaGetSymbolAddress(&p, g_state_scratch);
        state_out = (float*)p;
    }

    static bool attr_set = false;
    if (!attr_set) {
        cudaFuncSetAttribute(rwkv_fused, cudaFuncAttributeMaxDynamicSharedMemorySize,
                             SMEM_DYN);
        attr_set = true;
    }

    rwkv_fused<<<GRID, NTH, SMEM_DYN>>>(token, state, emb, ln0_w, ln0_b,
                                        ln1_w, ln1_b, ln2_w, ln2_b,
                                        att_key, att_value, att_recep, att_out,
                                        tm_k, tm_v, tm_r, t_first, t_decay,
                                        ffn_key, ffn_value, ffn_recep,
                                        ffn_tm_k, ffn_tm_r,
                                        lnout_w, lnout_b, head,
                                        logits, state_out);
}